// round 4
// baseline (speedup 1.0000x reference)
#include <cuda_runtime.h>
#include <math.h>

#define N_PTS    200000
#define M_TGT    256
#define ITERS    50
#define NTHREADS 256
#define NWARPS   (NTHREADS / 32)
#define U        8

#define EPS_NORM 1e-8f
#define EPS_SEP  (-1e-6f)

#define ALLONES 0xFFFFFFFFFFFFFFFFULL

// Allocation-free scratch (__device__ globals).
__device__ float4             d_p4[N_PTS];               // x,y,z, idx-bits in .w
__device__ float4             d_list[2][M_TGT][N_PTS];   // ping-pong survivor lists
__device__ unsigned long long d_best0[M_TGT];            // packed (key|idx), iter 0
__device__ unsigned long long d_best1[M_TGT];            // packed (key|idx), iter 1
__device__ int                d_len1[M_TGT];             // survivors after plane 0

// Monotone float->uint map: preserves < ordering incl. negatives.
__device__ __forceinline__ unsigned fkey(float f) {
    unsigned u = __float_as_uint(f);
    return (f < 0.0f) ? ~u : (u | 0x80000000u);
}

// Plane through point c as seen from target t (bit-identical everywhere it's used).
__device__ __forceinline__ float4 make_plane(float4 c, float tx, float ty, float tz) {
    float dx = c.x - tx, dy = c.y - ty, dz = c.z - tz;
    float inv = 1.0f / (sqrtf(dx * dx + dy * dy + dz * dz) + EPS_NORM);
    float A0 = dx * inv, A1 = dy * inv, A2 = dz * inv;
    return make_float4(A0, A1, A2, A0 * c.x + A1 * c.y + A2 * c.z);
}

__global__ void prep_kernel(const float* __restrict__ pc) {
    int j = blockIdx.x * blockDim.x + threadIdx.x;
    if (j < N_PTS) {
        float4 e;
        e.x = pc[3 * j + 0];
        e.y = pc[3 * j + 1];
        e.z = pc[3 * j + 2];
        e.w = __uint_as_float((unsigned)j);
        d_p4[j] = e;
    }
    if (blockIdx.x == 0 && threadIdx.x < M_TGT) {
        d_best0[threadIdx.x] = ALLONES;
        d_best1[threadIdx.x] = ALLONES;
        d_len1[threadIdx.x]  = 0;
    }
}

// Iteration-0 nearest neighbor, shared across targets.
// Block = 32 targets x 8 point-lanes; grid.x = point chunks, grid.y = target groups.
#define NN0_CHUNK 2048
__global__ __launch_bounds__(NTHREADS) void nn0_kernel(const float* __restrict__ targets) {
    const int tgt   = blockIdx.y * 32 + (threadIdx.x >> 3);
    const int lane8 = threadIdx.x & 7;
    const float tx = targets[3 * tgt + 0];
    const float ty = targets[3 * tgt + 1];
    const float tz = targets[3 * tgt + 2];
    const float t2 = tx * tx + ty * ty + tz * tz;

    const int start = blockIdx.x * NN0_CHUNK;
    const int end   = min(start + NN0_CHUNK, N_PTS);

    float best = INFINITY;
    int   bIdx = 0x7FFFFFFF;
    for (int i = start + lane8; i < end; i += 8) {
        float4 p = d_p4[i];
        float p2  = p.x * p.x + p.y * p.y + p.z * p.z;
        float key = (t2 + p2) - 2.0f * (tx * p.x + ty * p.y + tz * p.z);
        if (key < best || (key == best && i < bIdx)) { best = key; bIdx = i; }
    }
    #pragma unroll
    for (int o = 4; o > 0; o >>= 1) {
        float ov = __shfl_down_sync(0xFFFFFFFFu, best, o, 8);
        int   oi = __shfl_down_sync(0xFFFFFFFFu, bIdx, o, 8);
        if (ov < best || (ov == best && oi < bIdx)) { best = ov; bIdx = oi; }
    }
    if (lane8 == 0)
        atomicMin(&d_best0[tgt], ((unsigned long long)fkey(best) << 32) | (unsigned)bIdx);
}

// Iteration 1, shared point reads: block = 8 warps = 8 targets over one chunk
// (chunk stays L1-resident; each point's L2 read amortized 8x). Fuses plane-0 cut,
// iter-1 argmin (packed atomicMin), and survivor compaction (global atomicAdd;
// list order nondeterministic but output is order-invariant: argmin tie-breaks on
// original index and all later tests are element-wise).
#define C1_CHUNK 4096
__global__ __launch_bounds__(NTHREADS) void cut1_kernel(const float* __restrict__ targets) {
    const int warp = threadIdx.x >> 5;
    const int lane = threadIdx.x & 31;
    const int tgt  = blockIdx.y * NWARPS + warp;

    const float tx = targets[3 * tgt + 0];
    const float ty = targets[3 * tgt + 1];
    const float tz = targets[3 * tgt + 2];
    const float t2 = tx * tx + ty * ty + tz * tz;

    // Recompute plane 0 (warp-uniform; bit-identical to main_kernel's output calc).
    float4 c0 = d_p4[(unsigned)(d_best0[tgt] & 0xFFFFFFFFULL)];
    float4 pl = make_plane(c0, tx, ty, tz);

    const int start = blockIdx.x * C1_CHUNK;
    const int end   = min(start + C1_CHUNK, N_PTS);

    float4* __restrict__ outl = d_list[1][tgt];

    float best = INFINITY;
    int   bIdx = 0x7FFFFFFF;

    for (int i0 = start; i0 < end; i0 += 32) {
        int i = i0 + lane;
        bool act = (i < end);
        float4 p;
        if (act) {
            p = d_p4[i];
            float s = pl.x * p.x + pl.y * p.y + pl.z * p.z - pl.w;
            if (s >= EPS_SEP) act = false;          // separated -> drop
        }
        if (act) {
            float p2  = p.x * p.x + p.y * p.y + p.z * p.z;
            float key = (t2 + p2) - 2.0f * (tx * p.x + ty * p.y + tz * p.z);
            if (key < best || (key == best && i < bIdx)) { best = key; bIdx = i; }
        }
        unsigned bal = __ballot_sync(0xFFFFFFFFu, act);
        if (bal) {
            int base = 0;
            if (lane == 0) base = atomicAdd(&d_len1[tgt], __popc(bal));
            base = __shfl_sync(0xFFFFFFFFu, base, 0);
            if (act) outl[base + __popc(bal & ((1u << lane) - 1u))] = p;
        }
    }
    #pragma unroll
    for (int o = 16; o > 0; o >>= 1) {
        float ov = __shfl_down_sync(0xFFFFFFFFu, best, o);
        int   oi = __shfl_down_sync(0xFFFFFFFFu, bIdx, o);
        if (ov < best || (ov == best && oi < bIdx)) { best = ov; bIdx = oi; }
    }
    if (lane == 0 && best < INFINITY)
        atomicMin(&d_best1[tgt], ((unsigned long long)fkey(best) << 32) | (unsigned)bIdx);
}

// One block per target; iterations 2..49 on compacted lists.
__global__ __launch_bounds__(NTHREADS, 2) void main_kernel(
    const float* __restrict__ targets,
    float* __restrict__ out)
{
    const int t = blockIdx.x;
    float* __restrict__ out_a = out;                      // [ITERS][M][3]
    float* __restrict__ out_b = out + ITERS * M_TGT * 3;  // [ITERS][M]

    const int tid  = threadIdx.x;
    const int lane = tid & 31;
    const int warp = tid >> 5;

    const float tx = targets[3 * t + 0];
    const float ty = targets[3 * t + 1];
    const float tz = targets[3 * t + 2];
    const float t2 = tx * tx + ty * ty + tz * tz;

    __shared__ float s_plane[4];
    __shared__ int   s_len;
    __shared__ int   s_n;
    __shared__ float sv[NWARPS];
    __shared__ int   si[NWARPS];

    // Emit iter-0 and iter-1 outputs from the shared passes.
    if (tid == 0) {
        float4 c0 = d_p4[(unsigned)(d_best0[t] & 0xFFFFFFFFULL)];
        float4 p0 = make_plane(c0, tx, ty, tz);
        out_a[(0 * M_TGT + t) * 3 + 0] = p0.x;
        out_a[(0 * M_TGT + t) * 3 + 1] = p0.y;
        out_a[(0 * M_TGT + t) * 3 + 2] = p0.z;
        out_b[0 * M_TGT + t] = p0.w;

        unsigned long long pk1 = d_best1[t];
        unsigned bIdx1 = (pk1 == ALLONES) ? 0u : (unsigned)(pk1 & 0xFFFFFFFFULL);
        float4 c1 = d_p4[bIdx1];
        float4 p1 = make_plane(c1, tx, ty, tz);
        out_a[(1 * M_TGT + t) * 3 + 0] = p1.x;
        out_a[(1 * M_TGT + t) * 3 + 1] = p1.y;
        out_a[(1 * M_TGT + t) * 3 + 2] = p1.z;
        out_b[1 * M_TGT + t] = p1.w;

        s_plane[0] = p1.x; s_plane[1] = p1.y; s_plane[2] = p1.z; s_plane[3] = p1.w;
        s_n = d_len1[t];
    }
    __syncthreads();

    for (int it = 2; it < ITERS; ++it) {
        const float4* __restrict__ inl = d_list[(it - 1) & 1][t];
        const int n = s_n;
        float4* __restrict__ outl = d_list[it & 1][t];

        const float ax = s_plane[0], ay = s_plane[1], az = s_plane[2], bp = s_plane[3];

        if (tid == 0) s_len = 0;
        __syncthreads();

        float best = INFINITY;
        int   bIdx = 0;

        for (int cb = 0; cb < n; cb += NTHREADS * U) {
            float4 e[U];
            bool   act[U];
            #pragma unroll
            for (int u = 0; u < U; u++) {
                int i = cb + u * NTHREADS + tid;
                act[u] = (i < n);
                if (act[u]) e[u] = inl[i];
            }
            #pragma unroll
            for (int u = 0; u < U; u++) {
                if (act[u]) {
                    float px = e[u].x, py = e[u].y, pz = e[u].z;
                    float s = ax * px + ay * py + az * pz - bp;
                    if (s >= EPS_SEP) act[u] = false;   // separated -> drop
                    if (act[u]) {
                        float p2  = px * px + py * py + pz * pz;
                        float key = (t2 + p2) - 2.0f * (tx * px + ty * py + tz * pz);
                        int   idx = (int)__float_as_uint(e[u].w);
                        if (key < best || (key == best && idx < bIdx)) { best = key; bIdx = idx; }
                    }
                }
            }
            // Warp-aggregated compaction: 1 shared atomic per U chunks.
            unsigned bal[U];
            int cnt = 0;
            #pragma unroll
            for (int u = 0; u < U; u++) {
                bal[u] = __ballot_sync(0xFFFFFFFFu, act[u]);
                cnt += __popc(bal[u]);
            }
            int base = 0;
            if (lane == 0 && cnt) base = atomicAdd(&s_len, cnt);
            base = __shfl_sync(0xFFFFFFFFu, base, 0);
            unsigned lt = (1u << lane) - 1u;
            #pragma unroll
            for (int u = 0; u < U; u++) {
                if (act[u]) outl[base + __popc(bal[u] & lt)] = e[u];
                base += __popc(bal[u]);
            }
        }

        #pragma unroll
        for (int o = 16; o > 0; o >>= 1) {
            float ov = __shfl_down_sync(0xFFFFFFFFu, best, o);
            int   oi = __shfl_down_sync(0xFFFFFFFFu, bIdx, o);
            if (ov < best || (ov == best && oi < bIdx)) { best = ov; bIdx = oi; }
        }
        if (lane == 0) { sv[warp] = best; si[warp] = bIdx; }
        __syncthreads();

        if (tid == 0) {
            best = sv[0]; bIdx = si[0];
            #pragma unroll
            for (int k = 1; k < NWARPS; k++) {
                if (sv[k] < best || (sv[k] == best && si[k] < bIdx)) { best = sv[k]; bIdx = si[k]; }
            }
            // Empty list -> best = INF, bIdx = 0 (matches jnp.argmin on all-inf).
            float4 c = d_p4[bIdx];
            float4 pl = make_plane(c, tx, ty, tz);
            out_a[(it * M_TGT + t) * 3 + 0] = pl.x;
            out_a[(it * M_TGT + t) * 3 + 1] = pl.y;
            out_a[(it * M_TGT + t) * 3 + 2] = pl.z;
            out_b[it * M_TGT + t] = pl.w;
            s_plane[0] = pl.x; s_plane[1] = pl.y; s_plane[2] = pl.z; s_plane[3] = pl.w;
            s_n = s_len;
        }
        __syncthreads();

        if (s_n == 0) {
            // Mask stays empty: all later iterations repeat this output.
            if (tid == 0) {
                float A0 = s_plane[0], A1 = s_plane[1], A2 = s_plane[2], B = s_plane[3];
                for (int r = it + 1; r < ITERS; r++) {
                    out_a[(r * M_TGT + t) * 3 + 0] = A0;
                    out_a[(r * M_TGT + t) * 3 + 1] = A1;
                    out_a[(r * M_TGT + t) * 3 + 2] = A2;
                    out_b[r * M_TGT + t] = B;
                }
            }
            return;
        }
    }
}

extern "C" void kernel_launch(void* const* d_in, const int* in_sizes, int n_in,
                              void* d_out, int out_size) {
    const float* pointcloud = (const float*)d_in[0];   // [200000, 3]
    const float* targets    = (const float*)d_in[1];   // [256, 3]
    float* out = (float*)d_out;                        // a:[50,256,3] ++ b:[50,256]

    prep_kernel<<<(N_PTS + 255) / 256, 256>>>(pointcloud);
    dim3 g0((N_PTS + NN0_CHUNK - 1) / NN0_CHUNK, M_TGT / 32);
    nn0_kernel<<<g0, NTHREADS>>>(targets);
    dim3 g1((N_PTS + C1_CHUNK - 1) / C1_CHUNK, M_TGT / NWARPS);
    cut1_kernel<<<g1, NTHREADS>>>(targets);
    main_kernel<<<M_TGT, NTHREADS>>>(targets, out);
}

// round 7
// speedup vs baseline: 1.8304x; 1.8304x over previous
#include <cuda_runtime.h>
#include <math.h>

#define N_PTS    200000
#define M_TGT    256
#define ITERS    50
#define NTHREADS 256
#define NWARPS   (NTHREADS / 32)
#define U        8

#define EPS_NORM 1e-8f
#define EPS_SEP  (-1e-6f)

#define ALLONES 0xFFFFFFFFFFFFFFFFULL

// Grouped full-cloud passes: nn0/nn1 use 2048-pt chunks (32 targets share reads),
// cut2 uses 4096-pt chunks (8 targets share reads).
#define NN_CHUNK  2048
#define NN_NCHUNK ((N_PTS + NN_CHUNK - 1) / NN_CHUNK)    // 98
#define C2_CHUNK  4096
#define C2_NCHUNK ((N_PTS + C2_CHUNK - 1) / C2_CHUNK)    // 49
#define C2_TG     (M_TGT / NWARPS)                       // 32

// Allocation-free scratch (__device__ globals).
__device__ float4             d_p4[N_PTS];               // x,y,z, idx-bits in .w (L2-resident)
__device__ float4             d_list[2][M_TGT][N_PTS];   // ping-pong survivor lists (DRAM)
__device__ unsigned long long d_best0[M_TGT];            // packed (key|idx), iter 0 argmin
__device__ unsigned long long d_best1[M_TGT];            // packed (key|idx), iter 1 argmin
__device__ unsigned long long d_best2[M_TGT];            // packed (key|idx), iter 2 argmin
__device__ int                d_len2[M_TGT];             // survivors of planes 0&1
__device__ int                d_cnt[M_TGT][C2_NCHUNK];   // per-(tgt,chunk) survivor count
__device__ int                d_off[M_TGT][C2_NCHUNK];   // exclusive prefix of d_cnt

// Monotone float->uint map: preserves < ordering incl. negatives.
__device__ __forceinline__ unsigned fkey(float f) {
    unsigned u = __float_as_uint(f);
    return (f < 0.0f) ? ~u : (u | 0x80000000u);
}

// Plane through point c as seen from target t (bit-identical everywhere it's used).
__device__ __forceinline__ float4 make_plane(float4 c, float tx, float ty, float tz) {
    float dx = c.x - tx, dy = c.y - ty, dz = c.z - tz;
    float inv = 1.0f / (sqrtf(dx * dx + dy * dy + dz * dz) + EPS_NORM);
    float A0 = dx * inv, A1 = dy * inv, A2 = dz * inv;
    return make_float4(A0, A1, A2, A0 * c.x + A1 * c.y + A2 * c.z);
}

__device__ __forceinline__ unsigned best_idx(unsigned long long pk) {
    return (pk == ALLONES) ? 0u : (unsigned)(pk & 0xFFFFFFFFULL);
}

// alive = NOT separated by plane pl.
__device__ __forceinline__ bool alive1(float4 p, float4 pl) {
    return (pl.x * p.x + pl.y * p.y + pl.z * p.z - pl.w) < EPS_SEP;
}

__global__ void prep_kernel(const float* __restrict__ pc) {
    int j = blockIdx.x * blockDim.x + threadIdx.x;
    if (j < N_PTS) {
        float4 e;
        e.x = pc[3 * j + 0];
        e.y = pc[3 * j + 1];
        e.z = pc[3 * j + 2];
        e.w = __uint_as_float((unsigned)j);
        d_p4[j] = e;
    }
    if (blockIdx.x == 0 && threadIdx.x < M_TGT) {
        d_best0[threadIdx.x] = ALLONES;
        d_best1[threadIdx.x] = ALLONES;
        d_best2[threadIdx.x] = ALLONES;
    }
}

// Iteration-0 argmin. Block = 32 targets x 8 point-lanes sharing one chunk.
__global__ __launch_bounds__(NTHREADS) void nn0_kernel(const float* __restrict__ targets) {
    const int tgt   = blockIdx.y * 32 + (threadIdx.x >> 3);
    const int lane8 = threadIdx.x & 7;
    const float tx = targets[3 * tgt + 0];
    const float ty = targets[3 * tgt + 1];
    const float tz = targets[3 * tgt + 2];
    const float t2 = tx * tx + ty * ty + tz * tz;

    const int start = blockIdx.x * NN_CHUNK;
    const int end   = min(start + NN_CHUNK, N_PTS);

    float best = INFINITY;
    int   bIdx = 0x7FFFFFFF;
    for (int i = start + lane8; i < end; i += 8) {
        float4 p = d_p4[i];
        float p2  = p.x * p.x + p.y * p.y + p.z * p.z;
        float key = (t2 + p2) - 2.0f * (tx * p.x + ty * p.y + tz * p.z);
        if (key < best) { best = key; bIdx = i; }
    }
    #pragma unroll
    for (int o = 4; o > 0; o >>= 1) {
        float ov = __shfl_down_sync(0xFFFFFFFFu, best, o, 8);
        int   oi = __shfl_down_sync(0xFFFFFFFFu, bIdx, o, 8);
        if (ov < best || (ov == best && oi < bIdx)) { best = ov; bIdx = oi; }
    }
    if (lane8 == 0 && best < INFINITY)
        atomicMin(&d_best0[tgt], ((unsigned long long)fkey(best) << 32) | (unsigned)bIdx);
}

// Iteration-1 argmin over survivors of plane 0. Same layout as nn0; NO list write.
__global__ __launch_bounds__(NTHREADS) void nn1_kernel(const float* __restrict__ targets) {
    const int tgt   = blockIdx.y * 32 + (threadIdx.x >> 3);
    const int lane8 = threadIdx.x & 7;
    const float tx = targets[3 * tgt + 0];
    const float ty = targets[3 * tgt + 1];
    const float tz = targets[3 * tgt + 2];
    const float t2 = tx * tx + ty * ty + tz * tz;

    float4 pl0 = make_plane(d_p4[best_idx(d_best0[tgt])], tx, ty, tz);

    const int start = blockIdx.x * NN_CHUNK;
    const int end   = min(start + NN_CHUNK, N_PTS);

    float best = INFINITY;
    int   bIdx = 0x7FFFFFFF;
    for (int i = start + lane8; i < end; i += 8) {
        float4 p = d_p4[i];
        if (alive1(p, pl0)) {
            float p2  = p.x * p.x + p.y * p.y + p.z * p.z;
            float key = (t2 + p2) - 2.0f * (tx * p.x + ty * p.y + tz * p.z);
            if (key < best) { best = key; bIdx = i; }
        }
    }
    #pragma unroll
    for (int o = 4; o > 0; o >>= 1) {
        float ov = __shfl_down_sync(0xFFFFFFFFu, best, o, 8);
        int   oi = __shfl_down_sync(0xFFFFFFFFu, bIdx, o, 8);
        if (ov < best || (ov == best && oi < bIdx)) { best = ov; bIdx = oi; }
    }
    if (lane8 == 0 && best < INFINITY)
        atomicMin(&d_best1[tgt], ((unsigned long long)fkey(best) << 32) | (unsigned)bIdx);
}

// ---- cut2: three-phase (count / scan / write) list build, survivors of planes
//      0 AND 1 (exact: mask is the intersection of half-space predicates).
//      Also computes the iteration-2 argmin. Block = 8 warps = 8 targets. ----

__global__ __launch_bounds__(NTHREADS) void cut2_count_kernel(const float* __restrict__ targets) {
    const int warp  = threadIdx.x >> 5;
    const int lane  = threadIdx.x & 31;
    const int tgt   = blockIdx.y * NWARPS + warp;
    const int chunk = blockIdx.x;

    const float tx = targets[3 * tgt + 0];
    const float ty = targets[3 * tgt + 1];
    const float tz = targets[3 * tgt + 2];
    const float t2 = tx * tx + ty * ty + tz * tz;

    float4 pl0 = make_plane(d_p4[best_idx(d_best0[tgt])], tx, ty, tz);
    float4 pl1 = make_plane(d_p4[best_idx(d_best1[tgt])], tx, ty, tz);

    const int start = chunk * C2_CHUNK;
    const int end   = min(start + C2_CHUNK, N_PTS);

    int   cnt  = 0;
    float best = INFINITY;
    int   bIdx = 0x7FFFFFFF;

    for (int i = start + lane; i < end; i += 32) {
        float4 p = d_p4[i];
        if (alive1(p, pl0) && alive1(p, pl1)) {
            cnt++;
            float p2  = p.x * p.x + p.y * p.y + p.z * p.z;
            float key = (t2 + p2) - 2.0f * (tx * p.x + ty * p.y + tz * p.z);
            if (key < best) { best = key; bIdx = i; }
        }
    }
    #pragma unroll
    for (int o = 16; o > 0; o >>= 1) {
        float ov = __shfl_down_sync(0xFFFFFFFFu, best, o);
        int   oi = __shfl_down_sync(0xFFFFFFFFu, bIdx, o);
        int   oc = __shfl_down_sync(0xFFFFFFFFu, cnt, o);
        if (ov < best || (ov == best && oi < bIdx)) { best = ov; bIdx = oi; }
        cnt += oc;
    }
    if (lane == 0) {
        d_cnt[tgt][chunk] = cnt;
        if (best < INFINITY)
            atomicMin(&d_best2[tgt], ((unsigned long long)fkey(best) << 32) | (unsigned)bIdx);
    }
}

// One thread per target: serial exclusive scan over chunks (tiny).
__global__ void cut2_scan_kernel() {
    int t = threadIdx.x;
    int run = 0;
    for (int c = 0; c < C2_NCHUNK; c++) {
        d_off[t][c] = run;
        run += d_cnt[t][c];
    }
    d_len2[t] = run;
}

__global__ __launch_bounds__(NTHREADS) void cut2_write_kernel(const float* __restrict__ targets) {
    const int warp  = threadIdx.x >> 5;
    const int lane  = threadIdx.x & 31;
    const int tgt   = blockIdx.y * NWARPS + warp;
    const int chunk = blockIdx.x;

    const float tx = targets[3 * tgt + 0];
    const float ty = targets[3 * tgt + 1];
    const float tz = targets[3 * tgt + 2];

    float4 pl0 = make_plane(d_p4[best_idx(d_best0[tgt])], tx, ty, tz);
    float4 pl1 = make_plane(d_p4[best_idx(d_best1[tgt])], tx, ty, tz);

    const int start = chunk * C2_CHUNK;
    const int end   = min(start + C2_CHUNK, N_PTS);

    float4* __restrict__ outl = d_list[0][tgt];   // it=3 reads d_list[(3-1)&1] = d_list[0]
    int base = d_off[tgt][chunk];

    for (int i0 = start; i0 < end; i0 += 32) {
        int i = i0 + lane;
        bool act = false;
        float4 p;
        if (i < end) {
            p = d_p4[i];
            act = alive1(p, pl0) && alive1(p, pl1);
        }
        unsigned bal = __ballot_sync(0xFFFFFFFFu, act);
        if (act) outl[base + __popc(bal & ((1u << lane) - 1u))] = p;
        base += __popc(bal);
    }
}

// One block per target; iterations 3..49 on compacted lists.
__global__ __launch_bounds__(NTHREADS, 2) void main_kernel(
    const float* __restrict__ targets,
    float* __restrict__ out)
{
    const int t = blockIdx.x;
    float* __restrict__ out_a = out;                      // [ITERS][M][3]
    float* __restrict__ out_b = out + ITERS * M_TGT * 3;  // [ITERS][M]

    const int tid  = threadIdx.x;
    const int lane = tid & 31;
    const int warp = tid >> 5;

    const float tx = targets[3 * t + 0];
    const float ty = targets[3 * t + 1];
    const float tz = targets[3 * t + 2];
    const float t2 = tx * tx + ty * ty + tz * tz;

    __shared__ float s_plane[4];
    __shared__ int   s_len;
    __shared__ int   s_n;
    __shared__ float sv[NWARPS];
    __shared__ int   si[NWARPS];

    // Emit iters 0..2 from the shared passes; seed state for iter 3.
    if (tid == 0) {
        float4 p0 = make_plane(d_p4[best_idx(d_best0[t])], tx, ty, tz);
        out_a[(0 * M_TGT + t) * 3 + 0] = p0.x;
        out_a[(0 * M_TGT + t) * 3 + 1] = p0.y;
        out_a[(0 * M_TGT + t) * 3 + 2] = p0.z;
        out_b[0 * M_TGT + t] = p0.w;

        float4 p1 = make_plane(d_p4[best_idx(d_best1[t])], tx, ty, tz);
        out_a[(1 * M_TGT + t) * 3 + 0] = p1.x;
        out_a[(1 * M_TGT + t) * 3 + 1] = p1.y;
        out_a[(1 * M_TGT + t) * 3 + 2] = p1.z;
        out_b[1 * M_TGT + t] = p1.w;

        float4 p2 = make_plane(d_p4[best_idx(d_best2[t])], tx, ty, tz);
        out_a[(2 * M_TGT + t) * 3 + 0] = p2.x;
        out_a[(2 * M_TGT + t) * 3 + 1] = p2.y;
        out_a[(2 * M_TGT + t) * 3 + 2] = p2.z;
        out_b[2 * M_TGT + t] = p2.w;

        s_plane[0] = p2.x; s_plane[1] = p2.y; s_plane[2] = p2.z; s_plane[3] = p2.w;
        s_n = d_len2[t];
    }
    __syncthreads();

    for (int it = 3; it < ITERS; ++it) {
        const float4* __restrict__ inl = d_list[(it - 1) & 1][t];
        const int n = s_n;
        float4* __restrict__ outl = d_list[it & 1][t];
        const bool doWrite = (it < ITERS - 1);   // last iteration's list is never read

        const float ax = s_plane[0], ay = s_plane[1], az = s_plane[2], bp = s_plane[3];

        if (tid == 0) s_len = 0;
        __syncthreads();

        float best = INFINITY;
        int   bIdx = 0;

        for (int cb = 0; cb < n; cb += NTHREADS * U) {
            float4 e[U];
            bool   act[U];
            #pragma unroll
            for (int u = 0; u < U; u++) {
                int i = cb + u * NTHREADS + tid;
                act[u] = (i < n);
                if (act[u]) e[u] = inl[i];
            }
            #pragma unroll
            for (int u = 0; u < U; u++) {
                if (act[u]) {
                    float px = e[u].x, py = e[u].y, pz = e[u].z;
                    float s = ax * px + ay * py + az * pz - bp;
                    if (s >= EPS_SEP) act[u] = false;   // separated -> drop
                    if (act[u]) {
                        float p2  = px * px + py * py + pz * pz;
                        float key = (t2 + p2) - 2.0f * (tx * px + ty * py + tz * pz);
                        int   idx = (int)__float_as_uint(e[u].w);
                        if (key < best || (key == best && idx < bIdx)) { best = key; bIdx = idx; }
                    }
                }
            }
            // Warp-aggregated compaction: 1 shared atomic per U chunks.
            unsigned bal[U];
            int cnt = 0;
            #pragma unroll
            for (int u = 0; u < U; u++) {
                bal[u] = __ballot_sync(0xFFFFFFFFu, act[u]);
                cnt += __popc(bal[u]);
            }
            int base = 0;
            if (lane == 0 && cnt) base = atomicAdd(&s_len, cnt);
            base = __shfl_sync(0xFFFFFFFFu, base, 0);
            unsigned lt = (1u << lane) - 1u;
            if (doWrite) {
                #pragma unroll
                for (int u = 0; u < U; u++) {
                    if (act[u]) outl[base + __popc(bal[u] & lt)] = e[u];
                    base += __popc(bal[u]);
                }
            }
        }

        #pragma unroll
        for (int o = 16; o > 0; o >>= 1) {
            float ov = __shfl_down_sync(0xFFFFFFFFu, best, o);
            int   oi = __shfl_down_sync(0xFFFFFFFFu, bIdx, o);
            if (ov < best || (ov == best && oi < bIdx)) { best = ov; bIdx = oi; }
        }
        if (lane == 0) { sv[warp] = best; si[warp] = bIdx; }
        __syncthreads();

        if (tid == 0) {
            best = sv[0]; bIdx = si[0];
            #pragma unroll
            for (int k = 1; k < NWARPS; k++) {
                if (sv[k] < best || (sv[k] == best && si[k] < bIdx)) { best = sv[k]; bIdx = si[k]; }
            }
            // Empty list -> best = INF, bIdx = 0 (matches jnp.argmin on all-inf).
            float4 c = d_p4[bIdx];
            float4 pl = make_plane(c, tx, ty, tz);
            out_a[(it * M_TGT + t) * 3 + 0] = pl.x;
            out_a[(it * M_TGT + t) * 3 + 1] = pl.y;
            out_a[(it * M_TGT + t) * 3 + 2] = pl.z;
            out_b[it * M_TGT + t] = pl.w;
            s_plane[0] = pl.x; s_plane[1] = pl.y; s_plane[2] = pl.z; s_plane[3] = pl.w;
            s_n = s_len;
        }
        __syncthreads();

        if (s_n == 0) {
            // Mask stays empty: all later iterations repeat this output.
            if (tid == 0) {
                float A0 = s_plane[0], A1 = s_plane[1], A2 = s_plane[2], B = s_plane[3];
                for (int r = it + 1; r < ITERS; r++) {
                    out_a[(r * M_TGT + t) * 3 + 0] = A0;
                    out_a[(r * M_TGT + t) * 3 + 1] = A1;
                    out_a[(r * M_TGT + t) * 3 + 2] = A2;
                    out_b[r * M_TGT + t] = B;
                }
            }
            return;
        }
    }
}

extern "C" void kernel_launch(void* const* d_in, const int* in_sizes, int n_in,
                              void* d_out, int out_size) {
    const float* pointcloud = (const float*)d_in[0];   // [200000, 3]
    const float* targets    = (const float*)d_in[1];   // [256, 3]
    float* out = (float*)d_out;                        // a:[50,256,3] ++ b:[50,256]

    prep_kernel<<<(N_PTS + 255) / 256, 256>>>(pointcloud);
    dim3 gnn(NN_NCHUNK, M_TGT / 32);
    nn0_kernel<<<gnn, NTHREADS>>>(targets);
    nn1_kernel<<<gnn, NTHREADS>>>(targets);
    dim3 g2(C2_NCHUNK, C2_TG);
    cut2_count_kernel<<<g2, NTHREADS>>>(targets);
    cut2_scan_kernel<<<1, M_TGT>>>();
    cut2_write_kernel<<<g2, NTHREADS>>>(targets);
    main_kernel<<<M_TGT, NTHREADS>>>(targets, out);
}